// round 7
// baseline (speedup 1.0000x reference)
#include <cuda_runtime.h>
#include <cstdint>
#include <cstddef>

#define HID 512
#define TT  1024
#define NB  128
#define RTOT (NB*TT)

// ping-pong activation buffers (xp in / ys out, in place), 256 MB each
__device__ float g_bufA[(size_t)RTOT * HID];
__device__ float g_bufB[(size_t)RTOT * HID];

// ---------------- helpers ----------------
__device__ __forceinline__ uint32_t smem_u32(const void* p) {
    return (uint32_t)__cvta_generic_to_shared(p);
}
__device__ __forceinline__ uint32_t mapa_u32(uint32_t addr, uint32_t rank) {
    uint32_t r;
    asm("mapa.shared::cluster.u32 %0, %1, %2;" : "=r"(r) : "r"(addr), "r"(rank));
    return r;
}
__device__ __forceinline__ void st_cluster_f32(uint32_t addr, float v) {
    asm volatile("st.shared::cluster.f32 [%0], %1;" :: "r"(addr), "f"(v) : "memory");
}
__device__ __forceinline__ void cluster_sync_all() {
    asm volatile("barrier.cluster.arrive.aligned;" ::: "memory");
    asm volatile("barrier.cluster.wait.aligned;" ::: "memory");
}
__device__ __forceinline__ uint32_t ctarank() {
    uint32_t r; asm("mov.u32 %0, %%cluster_ctarank;" : "=r"(r)); return r;
}
__device__ __forceinline__ void mbar_init(uint32_t addr, uint32_t cnt) {
    asm volatile("mbarrier.init.shared.b64 [%0], %1;" :: "r"(addr), "r"(cnt) : "memory");
}
// release-arrive on the same-offset mbarrier in cluster CTA `rank`
__device__ __forceinline__ void mbar_arrive_remote(uint32_t local_addr, uint32_t rank) {
    uint32_t ra = mapa_u32(local_addr, rank);
    asm volatile("mbarrier.arrive.release.cluster.shared::cluster.b64 _, [%0];"
                 :: "r"(ra) : "memory");
}
// acquire-wait (cluster scope) on a local mbarrier, parity-based
__device__ __forceinline__ void mbar_wait(uint32_t addr, uint32_t parity) {
    asm volatile(
        "{\n\t.reg .pred P;\n"
        "WAIT_%=:\n\t"
        "mbarrier.try_wait.parity.acquire.cluster.shared::cta.b64 P, [%0], %1, 0x989680;\n\t"
        "@!P bra WAIT_%=;\n\t}"
        :: "r"(addr), "r"(parity) : "memory");
}
// accurate tanh, immune to --use_fast_math's tanh.approx
__device__ __forceinline__ float my_tanh(float x) {
    float e = __expf(2.0f * x);
    return 1.0f - 2.0f / (e + 1.0f);
}

// ---------------- xp0: (B*T,24) @ W_ih0^T -> (B*T,512) + bias ----------------
__global__ __launch_bounds__(256) void xp0_kernel(
    const float* __restrict__ x, const float* __restrict__ Wih,
    const float* __restrict__ bi, const float* __restrict__ bh,
    float* __restrict__ out)
{
    __shared__ float xs[32 * 24];
    int tid = threadIdx.x;
    int r0 = blockIdx.x * 32;
    int h0 = tid * 2;

    float w0[24], w1[24];
    const float4* wp0 = (const float4*)(Wih + (size_t)h0 * 24);
    #pragma unroll
    for (int i = 0; i < 6; i++) {
        float4 v = wp0[i];
        w0[4*i] = v.x; w0[4*i+1] = v.y; w0[4*i+2] = v.z; w0[4*i+3] = v.w;
    }
    const float4* wp1 = (const float4*)(Wih + (size_t)(h0 + 1) * 24);
    #pragma unroll
    for (int i = 0; i < 6; i++) {
        float4 v = wp1[i];
        w1[4*i] = v.x; w1[4*i+1] = v.y; w1[4*i+2] = v.z; w1[4*i+3] = v.w;
    }
    float bias0 = bi[h0] + bh[h0];
    float bias1 = bi[h0 + 1] + bh[h0 + 1];

    for (int i = tid; i < 32 * 24; i += 256) xs[i] = x[(size_t)r0 * 24 + i];
    __syncthreads();

    #pragma unroll 4
    for (int rr = 0; rr < 32; rr++) {
        float a0 = bias0, a1 = bias1;
        #pragma unroll
        for (int f = 0; f < 24; f++) {
            float xv = xs[rr * 24 + f];
            a0 = fmaf(w0[f], xv, a0);
            a1 = fmaf(w1[f], xv, a1);
        }
        *(float2*)(out + (size_t)(r0 + rr) * HID + h0) = make_float2(a0, a1);
    }
}

// ---------------- SGEMM: C[r][j] = bias[j] + sum_k A[r][k]*W[j][k] ----------------
#define GBM 128
#define GBN 128
#define GBK 16
__global__ __launch_bounds__(256, 2) void sgemm_kernel(
    const float* __restrict__ A, const float* __restrict__ W,
    const float* __restrict__ bi, const float* __restrict__ bh,
    float* __restrict__ C)
{
    __shared__ __align__(16) float As[2][GBK][GBM + 4];
    __shared__ __align__(16) float Ws[2][GBK][GBN + 4];

    int tid = threadIdx.x;
    int r0 = blockIdx.y * GBM;
    int j0 = blockIdx.x * GBN;
    int tx = tid & 15, ty = tid >> 4;

    float4 ra[2], rw[2];
    float acc[8][8];
    // fold bias into accumulator init (frees epilogue registers)
    #pragma unroll
    for (int j = 0; j < 8; j++) {
        int jj = j0 + tx * 8 + j;
        float bj = bi[jj] + bh[jj];
        #pragma unroll
        for (int i = 0; i < 8; i++) acc[i][j] = bj;
    }

    #pragma unroll
    for (int l = 0; l < 2; l++) {
        int idx = tid + l * 256;
        int r = idx >> 2, kq = idx & 3;
        ra[l] = *(const float4*)(A + (size_t)(r0 + r) * HID + kq * 4);
        rw[l] = *(const float4*)(W + (size_t)(j0 + r) * HID + kq * 4);
    }
    #pragma unroll
    for (int l = 0; l < 2; l++) {
        int idx = tid + l * 256;
        int r = idx >> 2, kq = idx & 3;
        As[0][kq*4+0][r] = ra[l].x; As[0][kq*4+1][r] = ra[l].y;
        As[0][kq*4+2][r] = ra[l].z; As[0][kq*4+3][r] = ra[l].w;
        Ws[0][kq*4+0][r] = rw[l].x; Ws[0][kq*4+1][r] = rw[l].y;
        Ws[0][kq*4+2][r] = rw[l].z; Ws[0][kq*4+3][r] = rw[l].w;
    }
    __syncthreads();

    for (int kt = 0; kt < HID / GBK; kt++) {
        int buf = kt & 1;
        if (kt + 1 < HID / GBK) {
            int kbase = (kt + 1) * GBK;
            #pragma unroll
            for (int l = 0; l < 2; l++) {
                int idx = tid + l * 256;
                int r = idx >> 2, kq = idx & 3;
                ra[l] = *(const float4*)(A + (size_t)(r0 + r) * HID + kbase + kq * 4);
                rw[l] = *(const float4*)(W + (size_t)(j0 + r) * HID + kbase + kq * 4);
            }
        }
        #pragma unroll
        for (int k = 0; k < GBK; k++) {
            float4 a0 = *(const float4*)&As[buf][k][ty * 8];
            float4 a1 = *(const float4*)&As[buf][k][ty * 8 + 4];
            float4 b0 = *(const float4*)&Ws[buf][k][tx * 8];
            float4 b1 = *(const float4*)&Ws[buf][k][tx * 8 + 4];
            float av[8] = {a0.x, a0.y, a0.z, a0.w, a1.x, a1.y, a1.z, a1.w};
            float bv[8] = {b0.x, b0.y, b0.z, b0.w, b1.x, b1.y, b1.z, b1.w};
            #pragma unroll
            for (int i = 0; i < 8; i++)
                #pragma unroll
                for (int j = 0; j < 8; j++)
                    acc[i][j] = fmaf(av[i], bv[j], acc[i][j]);
        }
        if (kt + 1 < HID / GBK) {
            int nb = buf ^ 1;
            #pragma unroll
            for (int l = 0; l < 2; l++) {
                int idx = tid + l * 256;
                int r = idx >> 2, kq = idx & 3;
                As[nb][kq*4+0][r] = ra[l].x; As[nb][kq*4+1][r] = ra[l].y;
                As[nb][kq*4+2][r] = ra[l].z; As[nb][kq*4+3][r] = ra[l].w;
                Ws[nb][kq*4+0][r] = rw[l].x; Ws[nb][kq*4+1][r] = rw[l].y;
                Ws[nb][kq*4+2][r] = rw[l].z; Ws[nb][kq*4+3][r] = rw[l].w;
            }
        }
        __syncthreads();
    }

    #pragma unroll
    for (int i = 0; i < 8; i++) {
        int row = r0 + ty * 8 + i;
        float4 o0 = make_float4(acc[i][0], acc[i][1], acc[i][2], acc[i][3]);
        float4 o1 = make_float4(acc[i][4], acc[i][5], acc[i][6], acc[i][7]);
        *(float4*)(C + (size_t)row * HID + j0 + tx * 8)     = o0;
        *(float4*)(C + (size_t)row * HID + j0 + tx * 8 + 4) = o1;
    }
}

// ---------------- recurrence: 8-CTA cluster, W_hh in registers, mbarrier sync ----------------
// grid = 128 CTAs (16 clusters x 8), 512 threads. CTA rank c owns W_hh rows
// [64c, 64c+64). thread tid: j = tid>>3 (out row), g = tid&7 (k-split lane AND
// batch lane), s = (g+j)&7 (chunk rotation -> conflict-free LDS). Per step:
// 8 batch x 64-k partial dots, 3-level shfl allreduce over g, lane g==b
// finalizes batch b; new h pushed to all 8 CTAs via st.shared::cluster, then
// __syncthreads + 8 release-arrives on remote mbarriers. Next step starts with
// one acquire try_wait (no cluster barrier, no L1 flush in the loop).
__global__ __launch_bounds__(512, 1) __cluster_dims__(8, 1, 1)
void rnn_kernel(float* __restrict__ xp, const float* __restrict__ Whh, int T,
                int writeAll)
{
    __shared__ __align__(16) float hs[2][8][8][68];
    __shared__ __align__(16) float xps[2][8][64];
    __shared__ __align__(8) unsigned long long mbars[2];

    int tid = threadIdx.x;
    int j = tid >> 3, g = tid & 7;
    int s = (g + j) & 7;
    uint32_t crank = ctarank();
    int cid = blockIdx.x >> 3;
    int b0  = cid * 8;
    int jg  = (int)crank * 64 + j;

    // W slice -> registers (64 floats)
    float w[64];
    const float4* wp = (const float4*)(Whh + (size_t)jg * HID + s * 64);
    #pragma unroll
    for (int i = 0; i < 16; i++) {
        float4 v = wp[i];
        w[4*i] = v.x; w[4*i+1] = v.y; w[4*i+2] = v.z; w[4*i+3] = v.w;
    }

    // DSMEM store targets: &hs[0][g][crank][j] in each cluster CTA
    uint32_t dst[8];
    {
        uint32_t a0 = smem_u32(&hs[0][g][crank][j]);
        #pragma unroll
        for (int r = 0; r < 8; r++) dst[r] = mapa_u32(a0, (uint32_t)r);
    }
    const uint32_t BUFOFF = (uint32_t)(8 * 8 * 68 * 4);
    uint32_t mb0 = smem_u32(&mbars[0]);
    uint32_t mb1 = smem_u32(&mbars[1]);

    if (tid == 0) { mbar_init(mb0, 8); mbar_init(mb1, 8); }

    // h_{-1} = 0
    for (int i = tid; i < 8 * 8 * 68; i += 512) ((float*)hs[0])[i] = 0.0f;

    // stage xp[t=0]
    int bb = tid >> 6, jj = tid & 63;
    xps[0][bb][jj] = xp[((size_t)(b0 + bb) * T + 0) * HID + crank * 64 + jj];
    __syncthreads();
    cluster_sync_all();   // mbarriers + initial state visible cluster-wide

    #pragma unroll 2
    for (int t = 0; t < T; t++) {
        int cur = t & 1, nxt = cur ^ 1;

        if (t > 0) mbar_wait(cur ? mb1 : mb0, (uint32_t)(((t - 1) >> 1) & 1));

        // prefetch next xp slice
        float xnext = 0.0f;
        if (t + 1 < T)
            xnext = xp[((size_t)(b0 + bb) * T + (t + 1)) * HID + crank * 64 + jj];

        float acc[8];
        #pragma unroll
        for (int b = 0; b < 8; b++) {
            const float4* hb = (const float4*)&hs[cur][b][s][0];
            float a0 = 0.f, a1 = 0.f, a2 = 0.f, a3 = 0.f;
            #pragma unroll
            for (int i = 0; i < 16; i++) {
                float4 hv = hb[i];
                a0 = fmaf(w[4*i],   hv.x, a0);
                a1 = fmaf(w[4*i+1], hv.y, a1);
                a2 = fmaf(w[4*i+2], hv.z, a2);
                a3 = fmaf(w[4*i+3], hv.w, a3);
            }
            acc[b] = (a0 + a1) + (a2 + a3);
        }
        #pragma unroll
        for (int b = 0; b < 8; b++) {
            acc[b] += __shfl_xor_sync(0xffffffffu, acc[b], 1);
            acc[b] += __shfl_xor_sync(0xffffffffu, acc[b], 2);
            acc[b] += __shfl_xor_sync(0xffffffffu, acc[b], 4);
        }
        float myacc = acc[0];
        #pragma unroll
        for (int b = 1; b < 8; b++) if (g == b) myacc = acc[b];

        float hnew = my_tanh(xps[cur][g][j] + myacc);

        if (t + 1 < T) {
            // push hnew into hs[nxt] of all 8 cluster CTAs
            uint32_t off = nxt ? BUFOFF : 0u;
            #pragma unroll
            for (int r = 0; r < 8; r++) st_cluster_f32(dst[r] + off, hnew);
            // stage next xp locally
            xps[nxt][bb][jj] = xnext;
        }

        __syncthreads();   // all local stores (DSMEM + xps) ordered before arrives

        if (t + 1 < T && tid < 8)
            mbar_arrive_remote(nxt ? mb1 : mb0, (uint32_t)tid);

        // ys write off the critical path
        if (writeAll || t == T - 1)
            xp[((size_t)(b0 + g) * T + t) * HID + jg] = hnew;
    }
}

// ---------------- head: last = ys2[:,T-1,:]; silu(last@W1^T+b1)@W2^T+b2 ----------------
__global__ __launch_bounds__(256) void head_kernel(
    const float* __restrict__ ys, const float* __restrict__ W1,
    const float* __restrict__ b1, const float* __restrict__ W2,
    const float* __restrict__ b2, float* __restrict__ out)
{
    __shared__ float hrow[HID];
    __shared__ float z[1024];
    int b = blockIdx.x;
    int tid = threadIdx.x, w = tid >> 5, l = tid & 31;

    const float* src = ys + ((size_t)b * TT + (TT - 1)) * HID;
    for (int i = tid; i < HID; i += 256) hrow[i] = src[i];
    __syncthreads();

    for (int m = w; m < 1024; m += 8) {
        const float4* wr = (const float4*)(W1 + (size_t)m * HID);
        float a = 0.0f;
        #pragma unroll
        for (int i = 0; i < 4; i++) {
            float4 wv = wr[l + 32 * i];
            float4 hv = *(const float4*)&hrow[4 * (l + 32 * i)];
            a = fmaf(wv.x, hv.x, a); a = fmaf(wv.y, hv.y, a);
            a = fmaf(wv.z, hv.z, a); a = fmaf(wv.w, hv.w, a);
        }
        a += __shfl_xor_sync(0xffffffffu, a, 16);
        a += __shfl_xor_sync(0xffffffffu, a, 8);
        a += __shfl_xor_sync(0xffffffffu, a, 4);
        a += __shfl_xor_sync(0xffffffffu, a, 2);
        a += __shfl_xor_sync(0xffffffffu, a, 1);
        if (l == 0) {
            float zz = a + b1[m];
            z[m] = zz / (1.0f + __expf(-zz));   // silu
        }
    }
    __syncthreads();

    {
        const float4* wr = (const float4*)(W2 + (size_t)w * 1024);
        float a = 0.0f;
        #pragma unroll
        for (int i = 0; i < 8; i++) {
            float4 wv = wr[l + 32 * i];
            float4 zv = *(const float4*)&z[4 * (l + 32 * i)];
            a = fmaf(wv.x, zv.x, a); a = fmaf(wv.y, zv.y, a);
            a = fmaf(wv.z, zv.z, a); a = fmaf(wv.w, zv.w, a);
        }
        a += __shfl_xor_sync(0xffffffffu, a, 16);
        a += __shfl_xor_sync(0xffffffffu, a, 8);
        a += __shfl_xor_sync(0xffffffffu, a, 4);
        a += __shfl_xor_sync(0xffffffffu, a, 2);
        a += __shfl_xor_sync(0xffffffffu, a, 1);
        if (l == 0) out[b * 8 + w] = a + b2[w];
    }
}

// ---------------- launch ----------------
extern "C" void kernel_launch(void* const* d_in, const int* in_sizes, int n_in,
                              void* d_out, int out_size) {
    const float* x     = (const float*)d_in[0];
    const float* Wih0  = (const float*)d_in[1];
    const float* Whh0  = (const float*)d_in[2];
    const float* bih0  = (const float*)d_in[3];
    const float* bhh0  = (const float*)d_in[4];
    const float* Wih1  = (const float*)d_in[5];
    const float* Whh1  = (const float*)d_in[6];
    const float* bih1  = (const float*)d_in[7];
    const float* bhh1  = (const float*)d_in[8];
    const float* Wih2  = (const float*)d_in[9];
    const float* Whh2  = (const float*)d_in[10];
    const float* bih2  = (const float*)d_in[11];
    const float* bhh2  = (const float*)d_in[12];
    const float* W1    = (const float*)d_in[13];
    const float* b1    = (const float*)d_in[14];
    const float* W2    = (const float*)d_in[15];
    const float* b2    = (const float*)d_in[16];
    float* out = (float*)d_out;

    float* bufA; cudaGetSymbolAddress((void**)&bufA, g_bufA);
    float* bufB; cudaGetSymbolAddress((void**)&bufB, g_bufB);

    // layer 0: xp0 then recurrence in place
    xp0_kernel<<<RTOT / 32, 256>>>(x, Wih0, bih0, bhh0, bufA);
    rnn_kernel<<<128, 512>>>(bufA, Whh0, TT, 1);

    // layer 1
    sgemm_kernel<<<dim3(HID / GBN, RTOT / GBM), 256>>>(bufA, Wih1, bih1, bhh1, bufB);
    rnn_kernel<<<128, 512>>>(bufB, Whh1, TT, 1);

    // layer 2 (only the last timestep of ys is consumed by the head)
    sgemm_kernel<<<dim3(HID / GBN, RTOT / GBM), 256>>>(bufB, Wih2, bih2, bhh2, bufA);
    rnn_kernel<<<128, 512>>>(bufA, Whh2, TT, 0);

    // head
    head_kernel<<<NB, 256>>>(bufA, W1, b1, W2, b2, out);
}

// round 8
// speedup vs baseline: 1.0091x; 1.0091x over previous
#include <cuda_runtime.h>
#include <cstdint>
#include <cstddef>

#define HID 512
#define TT  1024
#define NB  128
#define RTOT (NB*TT)

// ping-pong activation buffers (xp in / ys out, in place), 256 MB each
__device__ float g_bufA[(size_t)RTOT * HID];
__device__ float g_bufB[(size_t)RTOT * HID];

// ---------------- helpers ----------------
__device__ __forceinline__ uint32_t smem_u32(const void* p) {
    return (uint32_t)__cvta_generic_to_shared(p);
}
__device__ __forceinline__ uint32_t mapa_u32(uint32_t addr, uint32_t rank) {
    uint32_t r;
    asm("mapa.shared::cluster.u32 %0, %1, %2;" : "=r"(r) : "r"(addr), "r"(rank));
    return r;
}
__device__ __forceinline__ void st_cluster_f32(uint32_t addr, float v) {
    asm volatile("st.shared::cluster.f32 [%0], %1;" :: "r"(addr), "f"(v) : "memory");
}
__device__ __forceinline__ void cluster_sync_all() {
    asm volatile("barrier.cluster.arrive.aligned;" ::: "memory");
    asm volatile("barrier.cluster.wait.aligned;" ::: "memory");
}
__device__ __forceinline__ uint32_t ctarank() {
    uint32_t r; asm("mov.u32 %0, %%cluster_ctarank;" : "=r"(r)); return r;
}
__device__ __forceinline__ void mbar_init(uint32_t addr, uint32_t cnt) {
    asm volatile("mbarrier.init.shared.b64 [%0], %1;" :: "r"(addr), "r"(cnt) : "memory");
}
// release-arrive on the same-offset mbarrier in cluster CTA `rank`
__device__ __forceinline__ void mbar_arrive_remote(uint32_t local_addr, uint32_t rank) {
    uint32_t ra = mapa_u32(local_addr, rank);
    asm volatile("mbarrier.arrive.release.cluster.shared::cluster.b64 _, [%0];"
                 :: "r"(ra) : "memory");
}
// acquire-wait (cluster scope) on a local mbarrier, parity-based
__device__ __forceinline__ void mbar_wait(uint32_t addr, uint32_t parity) {
    asm volatile(
        "{\n\t.reg .pred P;\n"
        "WAIT_%=:\n\t"
        "mbarrier.try_wait.parity.acquire.cluster.shared::cta.b64 P, [%0], %1, 0x989680;\n\t"
        "@!P bra WAIT_%=;\n\t}"
        :: "r"(addr), "r"(parity) : "memory");
}
// accurate tanh, immune to --use_fast_math's tanh.approx
__device__ __forceinline__ float my_tanh(float x) {
    float e = __expf(2.0f * x);
    return 1.0f - 2.0f / (e + 1.0f);
}

// ---------------- xp0: (B*T,24) @ W_ih0^T -> (B*T,512) + bias ----------------
__global__ __launch_bounds__(256) void xp0_kernel(
    const float* __restrict__ x, const float* __restrict__ Wih,
    const float* __restrict__ bi, const float* __restrict__ bh,
    float* __restrict__ out)
{
    __shared__ float xs[32 * 24];
    int tid = threadIdx.x;
    int r0 = blockIdx.x * 32;
    int h0 = tid * 2;

    float w0[24], w1[24];
    const float4* wp0 = (const float4*)(Wih + (size_t)h0 * 24);
    #pragma unroll
    for (int i = 0; i < 6; i++) {
        float4 v = wp0[i];
        w0[4*i] = v.x; w0[4*i+1] = v.y; w0[4*i+2] = v.z; w0[4*i+3] = v.w;
    }
    const float4* wp1 = (const float4*)(Wih + (size_t)(h0 + 1) * 24);
    #pragma unroll
    for (int i = 0; i < 6; i++) {
        float4 v = wp1[i];
        w1[4*i] = v.x; w1[4*i+1] = v.y; w1[4*i+2] = v.z; w1[4*i+3] = v.w;
    }
    float bias0 = bi[h0] + bh[h0];
    float bias1 = bi[h0 + 1] + bh[h0 + 1];

    for (int i = tid; i < 32 * 24; i += 256) xs[i] = x[(size_t)r0 * 24 + i];
    __syncthreads();

    #pragma unroll 4
    for (int rr = 0; rr < 32; rr++) {
        float a0 = bias0, a1 = bias1;
        #pragma unroll
        for (int f = 0; f < 24; f++) {
            float xv = xs[rr * 24 + f];
            a0 = fmaf(w0[f], xv, a0);
            a1 = fmaf(w1[f], xv, a1);
        }
        *(float2*)(out + (size_t)(r0 + rr) * HID + h0) = make_float2(a0, a1);
    }
}

// ---------------- SGEMM: C[r][j] = bias[j] + sum_k A[r][k]*W[j][k] ----------------
#define GBM 128
#define GBN 128
#define GBK 16
__global__ __launch_bounds__(256, 2) void sgemm_kernel(
    const float* __restrict__ A, const float* __restrict__ W,
    const float* __restrict__ bi, const float* __restrict__ bh,
    float* __restrict__ C)
{
    __shared__ __align__(16) float As[2][GBK][GBM + 4];
    __shared__ __align__(16) float Ws[2][GBK][GBN + 4];

    int tid = threadIdx.x;
    int r0 = blockIdx.y * GBM;
    int j0 = blockIdx.x * GBN;
    int tx = tid & 15, ty = tid >> 4;

    float4 ra[2], rw[2];
    float acc[8][8];
    // bias folded into accumulator init
    #pragma unroll
    for (int j = 0; j < 8; j++) {
        int jj = j0 + tx * 8 + j;
        float bj = bi[jj] + bh[jj];
        #pragma unroll
        for (int i = 0; i < 8; i++) acc[i][j] = bj;
    }

    #pragma unroll
    for (int l = 0; l < 2; l++) {
        int idx = tid + l * 256;
        int r = idx >> 2, kq = idx & 3;
        ra[l] = *(const float4*)(A + (size_t)(r0 + r) * HID + kq * 4);
        rw[l] = *(const float4*)(W + (size_t)(j0 + r) * HID + kq * 4);
    }
    #pragma unroll
    for (int l = 0; l < 2; l++) {
        int idx = tid + l * 256;
        int r = idx >> 2, kq = idx & 3;
        As[0][kq*4+0][r] = ra[l].x; As[0][kq*4+1][r] = ra[l].y;
        As[0][kq*4+2][r] = ra[l].z; As[0][kq*4+3][r] = ra[l].w;
        Ws[0][kq*4+0][r] = rw[l].x; Ws[0][kq*4+1][r] = rw[l].y;
        Ws[0][kq*4+2][r] = rw[l].z; Ws[0][kq*4+3][r] = rw[l].w;
    }
    __syncthreads();

    for (int kt = 0; kt < HID / GBK; kt++) {
        int buf = kt & 1;
        if (kt + 1 < HID / GBK) {
            int kbase = (kt + 1) * GBK;
            #pragma unroll
            for (int l = 0; l < 2; l++) {
                int idx = tid + l * 256;
                int r = idx >> 2, kq = idx & 3;
                ra[l] = *(const float4*)(A + (size_t)(r0 + r) * HID + kbase + kq * 4);
                rw[l] = *(const float4*)(W + (size_t)(j0 + r) * HID + kbase + kq * 4);
            }
        }
        #pragma unroll
        for (int k = 0; k < GBK; k++) {
            float4 a0 = *(const float4*)&As[buf][k][ty * 8];
            float4 a1 = *(const float4*)&As[buf][k][ty * 8 + 4];
            float4 b0 = *(const float4*)&Ws[buf][k][tx * 8];
            float4 b1 = *(const float4*)&Ws[buf][k][tx * 8 + 4];
            float av[8] = {a0.x, a0.y, a0.z, a0.w, a1.x, a1.y, a1.z, a1.w};
            float bv[8] = {b0.x, b0.y, b0.z, b0.w, b1.x, b1.y, b1.z, b1.w};
            #pragma unroll
            for (int i = 0; i < 8; i++)
                #pragma unroll
                for (int j = 0; j < 8; j++)
                    acc[i][j] = fmaf(av[i], bv[j], acc[i][j]);
        }
        if (kt + 1 < HID / GBK) {
            int nb = buf ^ 1;
            #pragma unroll
            for (int l = 0; l < 2; l++) {
                int idx = tid + l * 256;
                int r = idx >> 2, kq = idx & 3;
                As[nb][kq*4+0][r] = ra[l].x; As[nb][kq*4+1][r] = ra[l].y;
                As[nb][kq*4+2][r] = ra[l].z; As[nb][kq*4+3][r] = ra[l].w;
                Ws[nb][kq*4+0][r] = rw[l].x; Ws[nb][kq*4+1][r] = rw[l].y;
                Ws[nb][kq*4+2][r] = rw[l].z; Ws[nb][kq*4+3][r] = rw[l].w;
            }
        }
        __syncthreads();
    }

    #pragma unroll
    for (int i = 0; i < 8; i++) {
        int row = r0 + ty * 8 + i;
        float4 o0 = make_float4(acc[i][0], acc[i][1], acc[i][2], acc[i][3]);
        float4 o1 = make_float4(acc[i][4], acc[i][5], acc[i][6], acc[i][7]);
        *(float4*)(C + (size_t)row * HID + j0 + tx * 8)     = o0;
        *(float4*)(C + (size_t)row * HID + j0 + tx * 8 + 4) = o1;
    }
}

// ---------------- recurrence: 8-CTA cluster, W_hh in registers, mbarrier sync ----------------
// Register-diet version: per-thread live set ~95 regs so w4[16] (the 64-float
// W slice) stays register-resident (R6/R7 sat at the 128-reg cap and spilled
// it -> LDL reloads each step starved the FMA pipe).
//  - no unroll over t (halves temp pressure)
//  - shfl allreduce fused into the b-loop: 1 myacc reg instead of acc[8]
//  - DSMEM target addresses recomputed via mapa per store (no dst[8] array)
__global__ __launch_bounds__(512, 1) __cluster_dims__(8, 1, 1)
void rnn_kernel(float* __restrict__ xp, const float* __restrict__ Whh, int T,
                int writeAll)
{
    __shared__ __align__(16) float hs[2][8][8][68];
    __shared__ __align__(16) float xps[2][8][64];
    __shared__ __align__(8) unsigned long long mbars[2];

    int tid = threadIdx.x;
    int j = tid >> 3, g = tid & 7;
    int s = (g + j) & 7;
    uint32_t crank = ctarank();
    int b0 = (blockIdx.x >> 3) * 8;
    int jg = (int)crank * 64 + j;

    // W slice -> registers (16 float4 = 64 floats)
    float4 w4[16];
    {
        const float4* wp = (const float4*)(Whh + (size_t)jg * HID + s * 64);
        #pragma unroll
        for (int i = 0; i < 16; i++) w4[i] = wp[i];
    }

    const uint32_t BUFOFF = (uint32_t)(8 * 8 * 68 * 4);
    uint32_t dstbase = smem_u32(&hs[0][g][crank][j]); // same offset in every CTA
    uint32_t mb0 = smem_u32(&mbars[0]);
    uint32_t mb1 = smem_u32(&mbars[1]);

    if (tid == 0) { mbar_init(mb0, 8); mbar_init(mb1, 8); }

    // h_{-1} = 0
    for (int i = tid; i < 8 * 8 * 68; i += 512) ((float*)hs[0])[i] = 0.0f;

    // stage xp[t=0]
    int bb = tid >> 6, jj = tid & 63;
    xps[0][bb][jj] = xp[((size_t)(b0 + bb) * T + 0) * HID + crank * 64 + jj];
    __syncthreads();
    cluster_sync_all();   // mbarriers + initial state visible cluster-wide

    for (int t = 0; t < T; t++) {
        int cur = t & 1, nxt = cur ^ 1;

        if (t > 0) mbar_wait(cur ? mb1 : mb0, (uint32_t)(((t - 1) >> 1) & 1));

        // prefetch next xp slice (latency hides under the matvec)
        float xnext = 0.0f;
        if (t + 1 < T)
            xnext = xp[((size_t)(b0 + bb) * T + (t + 1)) * HID + crank * 64 + jj];

        float myacc = 0.0f;
        #pragma unroll
        for (int b = 0; b < 8; b++) {
            const float4* hb = (const float4*)&hs[cur][b][s][0];
            float a0 = 0.f, a1 = 0.f, a2 = 0.f, a3 = 0.f;
            #pragma unroll
            for (int i = 0; i < 16; i++) {
                float4 hv = hb[i];
                a0 = fmaf(w4[i].x, hv.x, a0);
                a1 = fmaf(w4[i].y, hv.y, a1);
                a2 = fmaf(w4[i].z, hv.z, a2);
                a3 = fmaf(w4[i].w, hv.w, a3);
            }
            float p = (a0 + a1) + (a2 + a3);
            p += __shfl_xor_sync(0xffffffffu, p, 1);
            p += __shfl_xor_sync(0xffffffffu, p, 2);
            p += __shfl_xor_sync(0xffffffffu, p, 4);
            if (g == b) myacc = p;   // lane g finalizes batch b == g
        }

        float hnew = my_tanh(xps[cur][g][j] + myacc);

        if (t + 1 < T) {
            // push hnew into hs[nxt] of all 8 cluster CTAs
            uint32_t off = nxt ? BUFOFF : 0u;
            #pragma unroll
            for (int r = 0; r < 8; r++)
                st_cluster_f32(mapa_u32(dstbase, (uint32_t)r) + off, hnew);
            // stage next xp locally
            xps[nxt][bb][jj] = xnext;
        }

        __syncthreads();   // local + cluster stores ordered before arrives

        if (t + 1 < T && tid < 8)
            mbar_arrive_remote(nxt ? mb1 : mb0, (uint32_t)tid);

        // ys write off the critical path
        if (writeAll || t == T - 1)
            xp[((size_t)(b0 + g) * T + t) * HID + jg] = hnew;
    }
}

// ---------------- head: last = ys2[:,T-1,:]; silu(last@W1^T+b1)@W2^T+b2 ----------------
__global__ __launch_bounds__(256) void head_kernel(
    const float* __restrict__ ys, const float* __restrict__ W1,
    const float* __restrict__ b1, const float* __restrict__ W2,
    const float* __restrict__ b2, float* __restrict__ out)
{
    __shared__ float hrow[HID];
    __shared__ float z[1024];
    int b = blockIdx.x;
    int tid = threadIdx.x, w = tid >> 5, l = tid & 31;

    const float* src = ys + ((size_t)b * TT + (TT - 1)) * HID;
    for (int i = tid; i < HID; i += 256) hrow[i] = src[i];
    __syncthreads();

    for (int m = w; m < 1024; m += 8) {
        const float4* wr = (const float4*)(W1 + (size_t)m * HID);
        float a = 0.0f;
        #pragma unroll
        for (int i = 0; i < 4; i++) {
            float4 wv = wr[l + 32 * i];
            float4 hv = *(const float4*)&hrow[4 * (l + 32 * i)];
            a = fmaf(wv.x, hv.x, a); a = fmaf(wv.y, hv.y, a);
            a = fmaf(wv.z, hv.z, a); a = fmaf(wv.w, hv.w, a);
        }
        a += __shfl_xor_sync(0xffffffffu, a, 16);
        a += __shfl_xor_sync(0xffffffffu, a, 8);
        a += __shfl_xor_sync(0xffffffffu, a, 4);
        a += __shfl_xor_sync(0xffffffffu, a, 2);
        a += __shfl_xor_sync(0xffffffffu, a, 1);
        if (l == 0) {
            float zz = a + b1[m];
            z[m] = zz / (1.0f + __expf(-zz));   // silu
        }
    }
    __syncthreads();

    {
        const float4* wr = (const float4*)(W2 + (size_t)w * 1024);
        float a = 0.0f;
        #pragma unroll
        for (int i = 0; i < 8; i++) {
            float4 wv = wr[l + 32 * i];
            float4 zv = *(const float4*)&z[4 * (l + 32 * i)];
            a = fmaf(wv.x, zv.x, a); a = fmaf(wv.y, zv.y, a);
            a = fmaf(wv.z, zv.z, a); a = fmaf(wv.w, zv.w, a);
        }
        a += __shfl_xor_sync(0xffffffffu, a, 16);
        a += __shfl_xor_sync(0xffffffffu, a, 8);
        a += __shfl_xor_sync(0xffffffffu, a, 4);
        a += __shfl_xor_sync(0xffffffffu, a, 2);
        a += __shfl_xor_sync(0xffffffffu, a, 1);
        if (l == 0) out[b * 8 + w] = a + b2[w];
    }
}

// ---------------- launch ----------------
extern "C" void kernel_launch(void* const* d_in, const int* in_sizes, int n_in,
                              void* d_out, int out_size) {
    const float* x     = (const float*)d_in[0];
    const float* Wih0  = (const float*)d_in[1];
    const float* Whh0  = (const float*)d_in[2];
    const float* bih0  = (const float*)d_in[3];
    const float* bhh0  = (const float*)d_in[4];
    const float* Wih1  = (const float*)d_in[5];
    const float* Whh1  = (const float*)d_in[6];
    const float* bih1  = (const float*)d_in[7];
    const float* bhh1  = (const float*)d_in[8];
    const float* Wih2  = (const float*)d_in[9];
    const float* Whh2  = (const float*)d_in[10];
    const float* bih2  = (const float*)d_in[11];
    const float* bhh2  = (const float*)d_in[12];
    const float* W1    = (const float*)d_in[13];
    const float* b1    = (const float*)d_in[14];
    const float* W2    = (const float*)d_in[15];
    const float* b2    = (const float*)d_in[16];
    float* out = (float*)d_out;

    float* bufA; cudaGetSymbolAddress((void**)&bufA, g_bufA);
    float* bufB; cudaGetSymbolAddress((void**)&bufB, g_bufB);

    // layer 0: xp0 then recurrence in place
    xp0_kernel<<<RTOT / 32, 256>>>(x, Wih0, bih0, bhh0, bufA);
    rnn_kernel<<<128, 512>>>(bufA, Whh0, TT, 1);

    // layer 1
    sgemm_kernel<<<dim3(HID / GBN, RTOT / GBM), 256>>>(bufA, Wih1, bih1, bhh1, bufB);
    rnn_kernel<<<128, 512>>>(bufB, Whh1, TT, 1);

    // layer 2 (only the last timestep of ys is consumed by the head)
    sgemm_kernel<<<dim3(HID / GBN, RTOT / GBM), 256>>>(bufB, Wih2, bih2, bhh2, bufA);
    rnn_kernel<<<128, 512>>>(bufA, Whh2, TT, 0);

    // head
    head_kernel<<<NB, 256>>>(bufA, W1, b1, W2, b2, out);
}

// round 9
// speedup vs baseline: 1.7556x; 1.7398x over previous
#include <cuda_runtime.h>
#include <cstdint>
#include <cstddef>

#define HID 512
#define TT  1024
#define NB  128
#define RTOT (NB*TT)

// ping-pong activation buffers (xp in / ys out, in place), 256 MB each
__device__ float g_bufA[(size_t)RTOT * HID];
__device__ float g_bufB[(size_t)RTOT * HID];

// ---------------- helpers ----------------
__device__ __forceinline__ uint32_t smem_u32(const void* p) {
    return (uint32_t)__cvta_generic_to_shared(p);
}
__device__ __forceinline__ uint32_t mapa_u32(uint32_t addr, uint32_t rank) {
    uint32_t r;
    asm("mapa.shared::cluster.u32 %0, %1, %2;" : "=r"(r) : "r"(addr), "r"(rank));
    return r;
}
__device__ __forceinline__ void st_cluster_f32(uint32_t addr, float v) {
    asm volatile("st.shared::cluster.f32 [%0], %1;" :: "r"(addr), "f"(v) : "memory");
}
__device__ __forceinline__ void cluster_sync_all() {
    asm volatile("barrier.cluster.arrive.aligned;" ::: "memory");
    asm volatile("barrier.cluster.wait.aligned;" ::: "memory");
}
__device__ __forceinline__ uint32_t ctarank() {
    uint32_t r; asm("mov.u32 %0, %%cluster_ctarank;" : "=r"(r)); return r;
}
__device__ __forceinline__ void mbar_init(uint32_t addr, uint32_t cnt) {
    asm volatile("mbarrier.init.shared.b64 [%0], %1;" :: "r"(addr), "r"(cnt) : "memory");
}
__device__ __forceinline__ void mbar_arrive_remote(uint32_t local_addr, uint32_t rank) {
    uint32_t ra = mapa_u32(local_addr, rank);
    asm volatile("mbarrier.arrive.release.cluster.shared::cluster.b64 _, [%0];"
                 :: "r"(ra) : "memory");
}
__device__ __forceinline__ void mbar_wait(uint32_t addr, uint32_t parity) {
    asm volatile(
        "{\n\t.reg .pred P;\n"
        "WAIT_%=:\n\t"
        "mbarrier.try_wait.parity.acquire.cluster.shared::cta.b64 P, [%0], %1, 0x989680;\n\t"
        "@!P bra WAIT_%=;\n\t}"
        :: "r"(addr), "r"(parity) : "memory");
}
// accurate tanh, immune to --use_fast_math's tanh.approx
__device__ __forceinline__ float my_tanh(float x) {
    float e = __expf(2.0f * x);
    return 1.0f - 2.0f / (e + 1.0f);
}
// butterfly-merge helper: keep the half matching this lane's bit, add partner's
__device__ __forceinline__ float bfly_merge(float lo, float hi, unsigned bit, int mask) {
    float keep = bit ? hi : lo;
    float send = bit ? lo : hi;
    return keep + __shfl_xor_sync(0xffffffffu, send, mask);
}

// ---------------- xp0: (B*T,24) @ W_ih0^T -> (B*T,512) + bias ----------------
__global__ __launch_bounds__(256) void xp0_kernel(
    const float* __restrict__ x, const float* __restrict__ Wih,
    const float* __restrict__ bi, const float* __restrict__ bh,
    float* __restrict__ out)
{
    __shared__ float xs[32 * 24];
    int tid = threadIdx.x;
    int r0 = blockIdx.x * 32;
    int h0 = tid * 2;

    float w0[24], w1[24];
    const float4* wp0 = (const float4*)(Wih + (size_t)h0 * 24);
    #pragma unroll
    for (int i = 0; i < 6; i++) {
        float4 v = wp0[i];
        w0[4*i] = v.x; w0[4*i+1] = v.y; w0[4*i+2] = v.z; w0[4*i+3] = v.w;
    }
    const float4* wp1 = (const float4*)(Wih + (size_t)(h0 + 1) * 24);
    #pragma unroll
    for (int i = 0; i < 6; i++) {
        float4 v = wp1[i];
        w1[4*i] = v.x; w1[4*i+1] = v.y; w1[4*i+2] = v.z; w1[4*i+3] = v.w;
    }
    float bias0 = bi[h0] + bh[h0];
    float bias1 = bi[h0 + 1] + bh[h0 + 1];

    for (int i = tid; i < 32 * 24; i += 256) xs[i] = x[(size_t)r0 * 24 + i];
    __syncthreads();

    #pragma unroll 4
    for (int rr = 0; rr < 32; rr++) {
        float a0 = bias0, a1 = bias1;
        #pragma unroll
        for (int f = 0; f < 24; f++) {
            float xv = xs[rr * 24 + f];
            a0 = fmaf(w0[f], xv, a0);
            a1 = fmaf(w1[f], xv, a1);
        }
        *(float2*)(out + (size_t)(r0 + rr) * HID + h0) = make_float2(a0, a1);
    }
}

// ---------------- SGEMM: C[r][j] = bias[j] + sum_k A[r][k]*W[j][k] ----------------
#define GBM 128
#define GBN 128
#define GBK 16
__global__ __launch_bounds__(256, 2) void sgemm_kernel(
    const float* __restrict__ A, const float* __restrict__ W,
    const float* __restrict__ bi, const float* __restrict__ bh,
    float* __restrict__ C)
{
    __shared__ __align__(16) float As[2][GBK][GBM + 4];
    __shared__ __align__(16) float Ws[2][GBK][GBN + 4];

    int tid = threadIdx.x;
    int r0 = blockIdx.y * GBM;
    int j0 = blockIdx.x * GBN;
    int tx = tid & 15, ty = tid >> 4;

    float4 ra[2], rw[2];
    float acc[8][8];
    #pragma unroll
    for (int j = 0; j < 8; j++) {
        int jj = j0 + tx * 8 + j;
        float bj = bi[jj] + bh[jj];
        #pragma unroll
        for (int i = 0; i < 8; i++) acc[i][j] = bj;
    }

    #pragma unroll
    for (int l = 0; l < 2; l++) {
        int idx = tid + l * 256;
        int r = idx >> 2, kq = idx & 3;
        ra[l] = *(const float4*)(A + (size_t)(r0 + r) * HID + kq * 4);
        rw[l] = *(const float4*)(W + (size_t)(j0 + r) * HID + kq * 4);
    }
    #pragma unroll
    for (int l = 0; l < 2; l++) {
        int idx = tid + l * 256;
        int r = idx >> 2, kq = idx & 3;
        As[0][kq*4+0][r] = ra[l].x; As[0][kq*4+1][r] = ra[l].y;
        As[0][kq*4+2][r] = ra[l].z; As[0][kq*4+3][r] = ra[l].w;
        Ws[0][kq*4+0][r] = rw[l].x; Ws[0][kq*4+1][r] = rw[l].y;
        Ws[0][kq*4+2][r] = rw[l].z; Ws[0][kq*4+3][r] = rw[l].w;
    }
    __syncthreads();

    for (int kt = 0; kt < HID / GBK; kt++) {
        int buf = kt & 1;
        if (kt + 1 < HID / GBK) {
            int kbase = (kt + 1) * GBK;
            #pragma unroll
            for (int l = 0; l < 2; l++) {
                int idx = tid + l * 256;
                int r = idx >> 2, kq = idx & 3;
                ra[l] = *(const float4*)(A + (size_t)(r0 + r) * HID + kbase + kq * 4);
                rw[l] = *(const float4*)(W + (size_t)(j0 + r) * HID + kbase + kq * 4);
            }
        }
        #pragma unroll
        for (int k = 0; k < GBK; k++) {
            float4 a0 = *(const float4*)&As[buf][k][ty * 8];
            float4 a1 = *(const float4*)&As[buf][k][ty * 8 + 4];
            float4 b0 = *(const float4*)&Ws[buf][k][tx * 8];
            float4 b1 = *(const float4*)&Ws[buf][k][tx * 8 + 4];
            float av[8] = {a0.x, a0.y, a0.z, a0.w, a1.x, a1.y, a1.z, a1.w};
            float bv[8] = {b0.x, b0.y, b0.z, b0.w, b1.x, b1.y, b1.z, b1.w};
            #pragma unroll
            for (int i = 0; i < 8; i++)
                #pragma unroll
                for (int j = 0; j < 8; j++)
                    acc[i][j] = fmaf(av[i], bv[j], acc[i][j]);
        }
        if (kt + 1 < HID / GBK) {
            int nb = buf ^ 1;
            #pragma unroll
            for (int l = 0; l < 2; l++) {
                int idx = tid + l * 256;
                int r = idx >> 2, kq = idx & 3;
                As[nb][kq*4+0][r] = ra[l].x; As[nb][kq*4+1][r] = ra[l].y;
                As[nb][kq*4+2][r] = ra[l].z; As[nb][kq*4+3][r] = ra[l].w;
                Ws[nb][kq*4+0][r] = rw[l].x; Ws[nb][kq*4+1][r] = rw[l].y;
                Ws[nb][kq*4+2][r] = rw[l].z; Ws[nb][kq*4+3][r] = rw[l].w;
            }
        }
        __syncthreads();
    }

    #pragma unroll
    for (int i = 0; i < 8; i++) {
        int row = r0 + ty * 8 + i;
        float4 o0 = make_float4(acc[i][0], acc[i][1], acc[i][2], acc[i][3]);
        float4 o1 = make_float4(acc[i][4], acc[i][5], acc[i][6], acc[i][7]);
        *(float4*)(C + (size_t)row * HID + j0 + tx * 8)     = o0;
        *(float4*)(C + (size_t)row * HID + j0 + tx * 8 + 4) = o1;
    }
}

// ---------------- recurrence: 8-CTA cluster, register-blocked matvec ----------------
// R8 was smem-BW bound: 2KB smem read / thread / step (TM=1,TK=64) = 8192
// crossbar cyc/step vs 4096 FMA cyc. New tile TM=4 x TK=16: 512B/thread/step
// -> 2048 crossbar cyc, FMA-bound.
//   warp w (0..15): local rows 4w..4w+3 ; lane l: k in [16l, 16l+16)
//   h layout per batch: float4 slot [i*32 + l] holds k = l*16 + i*4 + c
//     -> lane-consecutive 16B: warp-LDS = 4 conflict-free wavefronts
//   reduction: butterfly MERGE (31 shfl/thread): stage1 pairs (b, b+4) at
//     mask16, then masks 8/4/2/1. Lane l ends with batch ((l>>2)&3)|((l>>4)<<2),
//     row w*4 + (l&3).
__global__ __launch_bounds__(512, 1) __cluster_dims__(8, 1, 1)
void rnn_kernel(float* __restrict__ xp, const float* __restrict__ Whh, int T,
                int writeAll)
{
    __shared__ __align__(16) float4 hs4[2][8][128];   // [buf][batch][i*32+l]
    __shared__ __align__(16) float xps[2][8][68];     // padded (bank-safe)
    __shared__ __align__(8) unsigned long long mbars[2];

    int tid = threadIdx.x;
    int w = tid >> 5, l = tid & 31;
    uint32_t crank = ctarank();
    int b0 = (blockIdx.x >> 3) * 8;

    // W tile: rows crank*64 + 4w + m, k = 16l + 4i + c   (64 regs)
    float4 w4[4][4];
    #pragma unroll
    for (int m = 0; m < 4; m++) {
        const float4* wp = (const float4*)(Whh +
            (size_t)(crank * 64 + w * 4 + m) * HID + l * 16);
        #pragma unroll
        for (int i = 0; i < 4; i++) w4[m][i] = wp[i];
    }

    // output position this lane owns after the reduce
    int bout = ((l >> 2) & 3) | ((l >> 4) << 2);
    int jg   = (int)crank * 64 + w * 4 + (l & 3);
    // its slot inside a batch region of hs4 (float granularity)
    int l2 = jg >> 4, i0 = (jg >> 2) & 3, c = jg & 3;
    const uint32_t BUFOFF = (uint32_t)sizeof(float4) * 8 * 128;   // 16384 B
    uint32_t dstbase = smem_u32(&hs4[0][bout][i0 * 32 + l2]) + (uint32_t)c * 4;

    uint32_t mb0 = smem_u32(&mbars[0]);
    uint32_t mb1 = smem_u32(&mbars[1]);
    if (tid == 0) { mbar_init(mb0, 8); mbar_init(mb1, 8); }

    // h_{-1} = 0
    for (int i = tid; i < 8 * 128; i += 512)
        ((float4*)hs4[0])[i] = make_float4(0.f, 0.f, 0.f, 0.f);

    // stage xp[t=0]
    int bb = tid >> 6, jj = tid & 63;
    xps[0][bb][jj] = xp[((size_t)(b0 + bb) * T + 0) * HID + crank * 64 + jj];
    __syncthreads();
    cluster_sync_all();   // mbarriers + initial state visible cluster-wide

    for (int t = 0; t < T; t++) {
        int cur = t & 1, nxt = cur ^ 1;

        if (t > 0) mbar_wait(cur ? mb1 : mb0, (uint32_t)(((t - 1) >> 1) & 1));

        // prefetch next xp slice (latency hides under the matvec)
        float xnext = 0.0f;
        if (t + 1 < T)
            xnext = xp[((size_t)(b0 + bb) * T + (t + 1)) * HID + crank * 64 + jj];

        // ---- matvec + progressive reduce ----
        unsigned bit4 = (l >> 4) & 1;
        float r16[16];
        #pragma unroll
        for (int bp = 0; bp < 4; bp++) {
            const float4* h0 = &hs4[cur][bp][l];       // stride 32 slots per i
            const float4* h1 = &hs4[cur][bp + 4][l];
            float p0[4] = {0.f, 0.f, 0.f, 0.f};
            float p1[4] = {0.f, 0.f, 0.f, 0.f};
            #pragma unroll
            for (int i = 0; i < 4; i++) {
                float4 hv0 = h0[i * 32];
                float4 hv1 = h1[i * 32];
                #pragma unroll
                for (int m = 0; m < 4; m++) {
                    p0[m] = fmaf(w4[m][i].x, hv0.x, p0[m]);
                    p0[m] = fmaf(w4[m][i].y, hv0.y, p0[m]);
                    p0[m] = fmaf(w4[m][i].z, hv0.z, p0[m]);
                    p0[m] = fmaf(w4[m][i].w, hv0.w, p0[m]);
                    p1[m] = fmaf(w4[m][i].x, hv1.x, p1[m]);
                    p1[m] = fmaf(w4[m][i].y, hv1.y, p1[m]);
                    p1[m] = fmaf(w4[m][i].z, hv1.z, p1[m]);
                    p1[m] = fmaf(w4[m][i].w, hv1.w, p1[m]);
                }
            }
            #pragma unroll
            for (int m = 0; m < 4; m++)
                r16[bp * 4 + m] = bfly_merge(p0[m], p1[m], bit4, 16);
        }
        float r8[8];
        { unsigned b3 = (l >> 3) & 1;
          #pragma unroll
          for (int q = 0; q < 8; q++) r8[q] = bfly_merge(r16[q], r16[8 + q], b3, 8); }
        float r4[4];
        { unsigned b2 = (l >> 2) & 1;
          #pragma unroll
          for (int q = 0; q < 4; q++) r4[q] = bfly_merge(r8[q], r8[4 + q], b2, 4); }
        float r2[2];
        { unsigned b1 = (l >> 1) & 1;
          #pragma unroll
          for (int q = 0; q < 2; q++) r2[q] = bfly_merge(r4[q], r4[2 + q], b1, 2); }
        float r1 = bfly_merge(r2[0], r2[1], l & 1, 1);

        float hnew = my_tanh(xps[cur][bout][w * 4 + (l & 3)] + r1);

        if (t + 1 < T) {
            uint32_t off = nxt ? BUFOFF : 0u;
            #pragma unroll
            for (int r = 0; r < 8; r++)
                st_cluster_f32(mapa_u32(dstbase, (uint32_t)r) + off, hnew);
            xps[nxt][bb][jj] = xnext;
        }

        __syncthreads();   // local + cluster stores ordered before arrives

        if (t + 1 < T && tid < 8)
            mbar_arrive_remote(nxt ? mb1 : mb0, (uint32_t)tid);

        if (writeAll || t == T - 1)
            xp[((size_t)(b0 + bout) * T + t) * HID + jg] = hnew;
    }
}

// ---------------- head: last = ys2[:,T-1,:]; silu(last@W1^T+b1)@W2^T+b2 ----------------
__global__ __launch_bounds__(256) void head_kernel(
    const float* __restrict__ ys, const float* __restrict__ W1,
    const float* __restrict__ b1, const float* __restrict__ W2,
    const float* __restrict__ b2, float* __restrict__ out)
{
    __shared__ float hrow[HID];
    __shared__ float z[1024];
    int b = blockIdx.x;
    int tid = threadIdx.x, w = tid >> 5, l = tid & 31;

    const float* src = ys + ((size_t)b * TT + (TT - 1)) * HID;
    for (int i = tid; i < HID; i += 256) hrow[i] = src[i];
    __syncthreads();

    for (int m = w; m < 1024; m += 8) {
        const float4* wr = (const float4*)(W1 + (size_t)m * HID);
        float a = 0.0f;
        #pragma unroll
        for (int i = 0; i < 4; i++) {
            float4 wv = wr[l + 32 * i];
            float4 hv = *(const float4*)&hrow[4 * (l + 32 * i)];
            a = fmaf(wv.x, hv.x, a); a = fmaf(wv.y, hv.y, a);
            a = fmaf(wv.z, hv.z, a); a = fmaf(wv.w, hv.w, a);
        }
        a += __shfl_xor_sync(0xffffffffu, a, 16);
        a += __shfl_xor_sync(0xffffffffu, a, 8);
        a += __shfl_xor_sync(0xffffffffu, a, 4);
        a += __shfl_xor_sync(0xffffffffu, a, 2);
        a += __shfl_xor_sync(0xffffffffu, a, 1);
        if (l == 0) {
            float zz = a + b1[m];
            z[m] = zz / (1.0f + __expf(-zz));   // silu
        }
    }
    __syncthreads();

    {
        const float4* wr = (const float4*)(W2 + (size_t)w * 1024);
        float a = 0.0f;
        #pragma unroll
        for (int i = 0; i < 8; i++) {
            float4 wv = wr[l + 32 * i];
            float4 zv = *(const float4*)&z[4 * (l + 32 * i)];
            a = fmaf(wv.x, zv.x, a); a = fmaf(wv.y, zv.y, a);
            a = fmaf(wv.z, zv.z, a); a = fmaf(wv.w, zv.w, a);
        }
        a += __shfl_xor_sync(0xffffffffu, a, 16);
        a += __shfl_xor_sync(0xffffffffu, a, 8);
        a += __shfl_xor_sync(0xffffffffu, a, 4);
        a += __shfl_xor_sync(0xffffffffu, a, 2);
        a += __shfl_xor_sync(0xffffffffu, a, 1);
        if (l == 0) out[b * 8 + w] = a + b2[w];
    }
}

// ---------------- launch ----------------
extern "C" void kernel_launch(void* const* d_in, const int* in_sizes, int n_in,
                              void* d_out, int out_size) {
    const float* x     = (const float*)d_in[0];
    const float* Wih0  = (const float*)d_in[1];
    const float* Whh0  = (const float*)d_in[2];
    const float* bih0  = (const float*)d_in[3];
    const float* bhh0  = (const float*)d_in[4];
    const float* Wih1  = (const float*)d_in[5];
    const float* Whh1  = (const float*)d_in[6];
    const float* bih1  = (const float*)d_in[7];
    const float* bhh1  = (const float*)d_in[8];
    const float* Wih2  = (const float*)d_in[9];
    const float* Whh2  = (const float*)d_in[10];
    const float* bih2  = (const float*)d_in[11];
    const float* bhh2  = (const float*)d_in[12];
    const float* W1    = (const float*)d_in[13];
    const float* b1    = (const float*)d_in[14];
    const float* W2    = (const float*)d_in[15];
    const float* b2    = (const float*)d_in[16];
    float* out = (float*)d_out;

    float* bufA; cudaGetSymbolAddress((void**)&bufA, g_bufA);
    float* bufB; cudaGetSymbolAddress((void**)&bufB, g_bufB);

    // layer 0: xp0 then recurrence in place
    xp0_kernel<<<RTOT / 32, 256>>>(x, Wih0, bih0, bhh0, bufA);
    rnn_kernel<<<128, 512>>>(bufA, Whh0, TT, 1);

    // layer 1
    sgemm_kernel<<<dim3(HID / GBN, RTOT / GBM), 256>>>(bufA, Wih1, bih1, bhh1, bufB);
    rnn_kernel<<<128, 512>>>(bufB, Whh1, TT, 1);

    // layer 2 (only the last timestep of ys is consumed by the head)
    sgemm_kernel<<<dim3(HID / GBN, RTOT / GBM), 256>>>(bufB, Wih2, bih2, bhh2, bufA);
    rnn_kernel<<<128, 512>>>(bufA, Whh2, TT, 0);

    // head
    head_kernel<<<NB, 256>>>(bufA, W1, b1, W2, b2, out);
}